// round 1
// baseline (speedup 1.0000x reference)
#include <cuda_runtime.h>
#include <math.h>

#define N_NODES 100000
#define N_EDGES 1600000
#define NUSER   90000

// ---------------- scratch (device globals; no allocation allowed) ----------
__device__ __align__(16) float g_hp [N_NODES * 128];   // (N, H*F) = (N,128)
__device__ __align__(16) float g_out[N_NODES * 128];   // unnormalized aggregation
__device__ __align__(16) float g_den[N_NODES * 2];     // per (node, head) sum of exp
__device__ __align__(16) float g_as [N_NODES * 2];     // attn_src per (node, head)
__device__ __align__(16) float g_at [N_NODES * 2];     // attn_trg per (node, head)
__device__ __align__(16) float g_ta [NUSER  * 128];    // type_aware (n, k, d) k in {0,1}
__device__ __align__(16) float g_u  [NUSER  * 64];     // feat @ aa_w1^T
__device__ __align__(16) float g_v  [NUSER  * 128];    // ta @ aa_w2^T, row = n*2+k

// ---------------- GEMM: C[M x P] = A[M x 64] @ B[64 x P] -------------------
// MODE 0: B[k][c] = w[(c/64)*4096 + k*64 + (c%64)]   (hp GEMM, P=128)
// MODE 1: B[k][c] = braw[c*64 + k]                    (aa GEMMs, transposed, P=64)
template<int P, int MODE>
__global__ __launch_bounds__(256)
void gemm64(const float* __restrict__ A, const float* __restrict__ Braw,
            float* __restrict__ C, int M)
{
    constexpr int BM  = 128;
    constexpr int CPT = P / 16;              // cols per thread (8 or 4)
    constexpr int LDA = BM + 4;              // padded, 16B aligned stride

    extern __shared__ float smem[];
    float* As = smem;                        // [64][LDA]  (transposed: As[k][row])
    float* Bs = smem + 64 * LDA;             // [64][P]

    const int t    = threadIdx.x;
    const int row0 = blockIdx.x * BM;

    // load B
    #pragma unroll 4
    for (int i = t; i < 64 * P; i += 256) {
        int kk = i / P, c = i % P;
        float v;
        if (MODE == 0) v = Braw[(c >> 6) * 4096 + kk * 64 + (c & 63)];
        else           v = Braw[c * 64 + kk];
        Bs[kk * P + c] = v;
    }
    // load A (transposed into smem)
    #pragma unroll 4
    for (int i = t; i < BM * 16; i += 256) {
        int r  = i >> 4;
        int k4 = (i & 15) << 2;
        float4 a = make_float4(0.f, 0.f, 0.f, 0.f);
        if (row0 + r < M) a = *(const float4*)(A + (size_t)(row0 + r) * 64 + k4);
        As[(k4 + 0) * LDA + r] = a.x;
        As[(k4 + 1) * LDA + r] = a.y;
        As[(k4 + 2) * LDA + r] = a.z;
        As[(k4 + 3) * LDA + r] = a.w;
    }
    __syncthreads();

    const int cg = t & 15;   // col group
    const int rg = t >> 4;   // row group

    float acc[8][CPT];
    #pragma unroll
    for (int r = 0; r < 8; r++)
        #pragma unroll
        for (int c = 0; c < CPT; c++) acc[r][c] = 0.f;

    #pragma unroll
    for (int k = 0; k < 64; k++) {
        float4 a0 = *(const float4*)(As + k * LDA + rg * 8);
        float4 a1 = *(const float4*)(As + k * LDA + rg * 8 + 4);
        float a[8] = {a0.x, a0.y, a0.z, a0.w, a1.x, a1.y, a1.z, a1.w};
        float b[CPT];
        {
            float4 b0 = *(const float4*)(Bs + k * P + cg * CPT);
            b[0] = b0.x; b[1] = b0.y; b[2] = b0.z; b[3] = b0.w;
            if (CPT == 8) {
                float4 b1 = *(const float4*)(Bs + k * P + cg * CPT + 4);
                b[4] = b1.x; b[5] = b1.y; b[6] = b1.z; b[7] = b1.w;
            }
        }
        #pragma unroll
        for (int r = 0; r < 8; r++)
            #pragma unroll
            for (int c = 0; c < CPT; c++)
                acc[r][c] = fmaf(a[r], b[c], acc[r][c]);
    }

    #pragma unroll
    for (int r = 0; r < 8; r++) {
        int row = row0 + rg * 8 + r;
        if (row < M) {
            #pragma unroll
            for (int c4 = 0; c4 < CPT / 4; c4++) {
                float4 o = make_float4(acc[r][c4*4+0], acc[r][c4*4+1],
                                       acc[r][c4*4+2], acc[r][c4*4+3]);
                *(float4*)(C + (size_t)row * P + cg * CPT + c4 * 4) = o;
            }
        }
    }
}

// ---------------- per-node attention logits --------------------------------
// as[n,h] = sum_f hp[n,h,f]*asrc[h,f];  at[n,h] = sum_f hp[n,h,f]*atrg[h,f]
__global__ __launch_bounds__(256)
void attn_kernel(const float* __restrict__ hp,
                 const float* __restrict__ asrc, const float* __restrict__ atrg,
                 float* __restrict__ as_, float* __restrict__ at_)
{
    int w    = (blockIdx.x * blockDim.x + threadIdx.x) >> 5;
    int lane = threadIdx.x & 31;
    if (w >= N_NODES) return;
    int h = lane >> 4, sub = lane & 15;

    float4 v  = *(const float4*)(hp + (size_t)w * 128 + lane * 4);
    float4 s4 = *(const float4*)(asrc + lane * 4);   // lane*4 == h*64 + sub*4
    float4 t4 = *(const float4*)(atrg + lane * 4);
    float ps = v.x*s4.x + v.y*s4.y + v.z*s4.z + v.w*s4.w;
    float pt = v.x*t4.x + v.y*t4.y + v.z*t4.z + v.w*t4.w;
    #pragma unroll
    for (int o = 8; o > 0; o >>= 1) {
        ps += __shfl_xor_sync(0xffffffffu, ps, o);
        pt += __shfl_xor_sync(0xffffffffu, pt, o);
    }
    if (sub == 0) {
        as_[w * 2 + h] = ps;
        at_[w * 2 + h] = pt;
    }
}

// ---------------- zero out + den --------------------------------------------
__global__ void zero_kernel(float4* __restrict__ out4, float4* __restrict__ den4)
{
    int i = blockIdx.x * blockDim.x + threadIdx.x;
    const int NOUT4 = N_NODES * 32;      // 3.2M
    const int NDEN4 = N_NODES * 2 / 4;   // 50000
    float4 z = make_float4(0.f, 0.f, 0.f, 0.f);
    if (i < NOUT4)            out4[i] = z;
    else if (i < NOUT4+NDEN4) den4[i - NOUT4] = z;
}

// ---------------- edge kernel: one warp per edge ----------------------------
// w_h = exp(leaky(as[src,h] + at[trg,h])); den[trg,h] += w_h;
// out[trg, h, :] += w_h * hp[src, h, :]
__global__ __launch_bounds__(256)
void edge_kernel(const int* __restrict__ src, const int* __restrict__ trg,
                 const float* __restrict__ as_, const float* __restrict__ at_,
                 const float* __restrict__ hp,
                 float* __restrict__ out, float* __restrict__ den)
{
    int w    = (blockIdx.x * blockDim.x + threadIdx.x) >> 5;
    int lane = threadIdx.x & 31;
    if (w >= N_EDGES) return;

    int s = __ldg(src + w);
    int t = __ldg(trg + w);
    float2 a_s = *(const float2*)(as_ + 2 * s);
    float2 a_t = *(const float2*)(at_ + 2 * t);
    float e0 = a_s.x + a_t.x; e0 = (e0 > 0.f) ? e0 : 0.2f * e0;
    float e1 = a_s.y + a_t.y; e1 = (e1 > 0.f) ? e1 : 0.2f * e1;
    float w0 = expf(e0), w1 = expf(e1);

    if      (lane == 0)  atomicAdd(den + 2 * t,     w0);
    else if (lane == 16) atomicAdd(den + 2 * t + 1, w1);

    float wt = (lane < 16) ? w0 : w1;
    float4 v = *(const float4*)(hp + (size_t)s * 128 + lane * 4);
    float4 r = make_float4(v.x * wt, v.y * wt, v.z * wt, v.w * wt);
    atomicAdd((float4*)(out + (size_t)t * 128 + lane * 4), r);   // 128-bit RED (sm_90+)
}

// ---------------- normalize + head-mean into type_aware ---------------------
__global__ __launch_bounds__(256)
void xnorm_kernel(const float* __restrict__ out, const float* __restrict__ den,
                  float* __restrict__ ta, int layer)
{
    int i = blockIdx.x * blockDim.x + threadIdx.x;
    if (i >= NUSER * 64) return;
    int n = i >> 6, d = i & 63;
    float inv0 = 1.f / (den[2 * n]     + 1e-16f);
    float inv1 = 1.f / (den[2 * n + 1] + 1e-16f);
    float x = 0.5f * (out[n * 128 + d] * inv0 + out[n * 128 + 64 + d] * inv1);
    ta[n * 128 + layer * 64 + d] = x;
}

// ---------------- head: tanh-attention fusion + FC + log_softmax ------------
__global__ __launch_bounds__(256)
void head_kernel(const float* __restrict__ u, const float* __restrict__ v,
                 const float* __restrict__ ta,
                 const float* __restrict__ aam, const float* __restrict__ fcw,
                 const float* __restrict__ fcb, float* __restrict__ outp)
{
    int w    = (blockIdx.x * blockDim.x + threadIdx.x) >> 5;
    int lane = threadIdx.x & 31;
    if (w >= NUSER) return;
    int d1 = lane, d2 = lane + 32;

    float u1   = u[w * 64 + d1],            u2   = u[w * 64 + d2];
    float v01  = v[(2*w) * 64 + d1],        v02  = v[(2*w) * 64 + d2];
    float v11  = v[(2*w+1) * 64 + d1],      v12  = v[(2*w+1) * 64 + d2];
    float ta01 = ta[w * 128 + d1],          ta02 = ta[w * 128 + d2];
    float ta11 = ta[w * 128 + 64 + d1],     ta12 = ta[w * 128 + 64 + d2];
    float am1  = __ldg(aam + d1),           am2  = __ldg(aam + d2);

    float s0 = tanhf(u1 + v01) * am1 + tanhf(u2 + v02) * am2;
    float s1 = tanhf(u1 + v11) * am1 + tanhf(u2 + v12) * am2;
    #pragma unroll
    for (int o = 16; o > 0; o >>= 1) {
        s0 += __shfl_xor_sync(0xffffffffu, s0, o);
        s1 += __shfl_xor_sync(0xffffffffu, s1, o);
    }
    float m  = fmaxf(s0, s1);
    float e0 = expf(s0 - m), e1 = expf(s1 - m);
    float rb = 1.f / (e0 + e1);
    float b0 = e0 * rb, b1 = e1 * rb;

    float f1 = b0 * ta01 + b1 * ta11;
    float f2 = b0 * ta02 + b1 * ta12;

    float l0 = ta01 * __ldg(fcw + d1)        + ta02 * __ldg(fcw + d2)
             + ta11 * __ldg(fcw + 64 + d1)   + ta12 * __ldg(fcw + 64 + d2)
             + f1   * __ldg(fcw + 128 + d1)  + f2   * __ldg(fcw + 128 + d2);
    float l1 = ta01 * __ldg(fcw + 192 + d1)  + ta02 * __ldg(fcw + 192 + d2)
             + ta11 * __ldg(fcw + 256 + d1)  + ta12 * __ldg(fcw + 256 + d2)
             + f1   * __ldg(fcw + 320 + d1)  + f2   * __ldg(fcw + 320 + d2);
    #pragma unroll
    for (int o = 16; o > 0; o >>= 1) {
        l0 += __shfl_xor_sync(0xffffffffu, l0, o);
        l1 += __shfl_xor_sync(0xffffffffu, l1, o);
    }
    if (lane == 0) {
        l0 += __ldg(fcb + 0);
        l1 += __ldg(fcb + 1);
        float mm  = fmaxf(l0, l1);
        float lse = mm + logf(expf(l0 - mm) + expf(l1 - mm));
        outp[w * 2]     = l0 - lse;
        outp[w * 2 + 1] = l1 - lse;
    }
}

// ---------------- launch ----------------------------------------------------
extern "C" void kernel_launch(void* const* d_in, const int* in_sizes, int n_in,
                              void* d_out, int out_size)
{
    const float* h     = (const float*)d_in[0];
    const int*   src0  = (const int*)  d_in[1];
    const int*   trg0  = (const int*)  d_in[2];
    const int*   src1  = (const int*)  d_in[3];
    const int*   trg1  = (const int*)  d_in[4];
    const float* w0    = (const float*)d_in[5];
    const float* asrc0 = (const float*)d_in[6];
    const float* atrg0 = (const float*)d_in[7];
    const float* w1    = (const float*)d_in[8];
    const float* asrc1 = (const float*)d_in[9];
    const float* atrg1 = (const float*)d_in[10];
    const float* aaw1  = (const float*)d_in[11];
    const float* aaw2  = (const float*)d_in[12];
    const float* aam   = (const float*)d_in[13];
    const float* fcw   = (const float*)d_in[14];
    const float* fcb   = (const float*)d_in[15];
    float* out = (float*)d_out;

    float *hp, *og, *den, *as_, *at_, *ta, *u, *v;
    cudaGetSymbolAddress((void**)&hp,  g_hp);
    cudaGetSymbolAddress((void**)&og,  g_out);
    cudaGetSymbolAddress((void**)&den, g_den);
    cudaGetSymbolAddress((void**)&as_, g_as);
    cudaGetSymbolAddress((void**)&at_, g_at);
    cudaGetSymbolAddress((void**)&ta,  g_ta);
    cudaGetSymbolAddress((void**)&u,   g_u);
    cudaGetSymbolAddress((void**)&v,   g_v);

    const int SM128 = (64 * 132 + 64 * 128) * 4;   // 66560 B
    const int SM64  = (64 * 132 + 64 * 64)  * 4;   // 50176 B
    cudaFuncSetAttribute(gemm64<128,0>, cudaFuncAttributeMaxDynamicSharedMemorySize, SM128);
    cudaFuncSetAttribute(gemm64<64,1>,  cudaFuncAttributeMaxDynamicSharedMemorySize, SM64);

    const int GEMM_HP_BLK = (N_NODES + 127) / 128;        // 782
    const int ATTN_BLK    = N_NODES * 32 / 256;           // 12500
    const int ZERO_BLK    = (N_NODES * 32 + N_NODES * 2 / 4 + 255) / 256;
    const int EDGE_BLK    = N_EDGES * 32 / 256;           // 200000
    const int XN_BLK      = NUSER * 64 / 256;             // 22500
    const int HEAD_BLK    = NUSER * 32 / 256;             // 11250

    // ---- layer 0 ----
    gemm64<128,0><<<GEMM_HP_BLK, 256, SM128>>>(h, w0, hp, N_NODES);
    attn_kernel<<<ATTN_BLK, 256>>>(hp, asrc0, atrg0, as_, at_);
    zero_kernel<<<ZERO_BLK, 256>>>((float4*)og, (float4*)den);
    edge_kernel<<<EDGE_BLK, 256>>>(src0, trg0, as_, at_, hp, og, den);
    xnorm_kernel<<<XN_BLK, 256>>>(og, den, ta, 0);

    // ---- layer 1 ----
    gemm64<128,0><<<GEMM_HP_BLK, 256, SM128>>>(h, w1, hp, N_NODES);
    attn_kernel<<<ATTN_BLK, 256>>>(hp, asrc1, atrg1, as_, at_);
    zero_kernel<<<ZERO_BLK, 256>>>((float4*)og, (float4*)den);
    edge_kernel<<<EDGE_BLK, 256>>>(src1, trg1, as_, at_, hp, og, den);
    xnorm_kernel<<<XN_BLK, 256>>>(og, den, ta, 1);

    // ---- head ----
    gemm64<64,1><<<(NUSER + 127) / 128, 256, SM64>>>(h, aaw1, u, NUSER);
    gemm64<64,1><<<(NUSER * 2 + 127) / 128, 256, SM64>>>(ta, aaw2, v, NUSER * 2);
    head_kernel<<<HEAD_BLK, 256>>>(u, v, ta, aam, fcw, fcb, out);

    (void)in_sizes; (void)n_in; (void)out_size;
}

// round 2
// speedup vs baseline: 1.8015x; 1.8015x over previous
#include <cuda_runtime.h>
#include <math.h>

#define N_NODES 100000
#define N_EDGES 1600000
#define NUSER   90000
#define SCAN_CHUNK 512
#define NPART   ((NUSER + SCAN_CHUNK - 1) / SCAN_CHUNK)   // 176

// ---------------- scratch (device globals; no allocation allowed) ----------
__device__ __align__(16) float g_hp [N_NODES * 128];   // (N, H*F) = (N,128)
__device__ __align__(16) float g_as [N_NODES * 2];     // attn_src per (node, head)
__device__ __align__(16) float g_at [N_NODES * 2];     // attn_trg per (node, head)
__device__ __align__(16) float g_ta [NUSER  * 128];    // type_aware (n, k, d)
__device__ __align__(16) float g_u  [NUSER  * 64];     // feat @ aa_w1^T
__device__ __align__(16) float g_v  [NUSER  * 128];    // ta @ aa_w2^T, row = n*2+k
__device__ __align__(16) int   g_cnt[NUSER * 2];       // [0:NUSER)=counts, [NUSER:2N)=cursor
__device__ __align__(16) int   g_off[NUSER];           // CSR row offsets
__device__ __align__(16) int   g_part[256];            // scan partials
__device__ __align__(16) int   g_csr[N_EDGES];         // bucketed src ids

// ---------------- GEMM: C[M x P] = A[M x 64] @ B[64 x P] -------------------
// MODE 0: B[k][c] = w[(c/64)*4096 + k*64 + (c%64)]   (hp GEMM, P=128)
// MODE 1: B[k][c] = braw[c*64 + k]                    (aa GEMMs, transposed, P=64)
template<int P, int MODE>
__global__ __launch_bounds__(256)
void gemm64(const float* __restrict__ A, const float* __restrict__ Braw,
            float* __restrict__ C, int M)
{
    constexpr int BM  = 128;
    constexpr int CPT = P / 16;
    constexpr int LDA = BM + 4;

    extern __shared__ float smem[];
    float* As = smem;                        // [64][LDA]
    float* Bs = smem + 64 * LDA;             // [64][P]

    const int t    = threadIdx.x;
    const int row0 = blockIdx.x * BM;

    #pragma unroll 4
    for (int i = t; i < 64 * P; i += 256) {
        int kk = i / P, c = i % P;
        float v;
        if (MODE == 0) v = Braw[(c >> 6) * 4096 + kk * 64 + (c & 63)];
        else           v = Braw[c * 64 + kk];
        Bs[kk * P + c] = v;
    }
    #pragma unroll 4
    for (int i = t; i < BM * 16; i += 256) {
        int r  = i >> 4;
        int k4 = (i & 15) << 2;
        float4 a = make_float4(0.f, 0.f, 0.f, 0.f);
        if (row0 + r < M) a = *(const float4*)(A + (size_t)(row0 + r) * 64 + k4);
        As[(k4 + 0) * LDA + r] = a.x;
        As[(k4 + 1) * LDA + r] = a.y;
        As[(k4 + 2) * LDA + r] = a.z;
        As[(k4 + 3) * LDA + r] = a.w;
    }
    __syncthreads();

    const int cg = t & 15;
    const int rg = t >> 4;

    float acc[8][CPT];
    #pragma unroll
    for (int r = 0; r < 8; r++)
        #pragma unroll
        for (int c = 0; c < CPT; c++) acc[r][c] = 0.f;

    #pragma unroll
    for (int k = 0; k < 64; k++) {
        float4 a0 = *(const float4*)(As + k * LDA + rg * 8);
        float4 a1 = *(const float4*)(As + k * LDA + rg * 8 + 4);
        float a[8] = {a0.x, a0.y, a0.z, a0.w, a1.x, a1.y, a1.z, a1.w};
        float b[CPT];
        {
            float4 b0 = *(const float4*)(Bs + k * P + cg * CPT);
            b[0] = b0.x; b[1] = b0.y; b[2] = b0.z; b[3] = b0.w;
            if (CPT == 8) {
                float4 b1 = *(const float4*)(Bs + k * P + cg * CPT + 4);
                b[4] = b1.x; b[5] = b1.y; b[6] = b1.z; b[7] = b1.w;
            }
        }
        #pragma unroll
        for (int r = 0; r < 8; r++)
            #pragma unroll
            for (int c = 0; c < CPT; c++)
                acc[r][c] = fmaf(a[r], b[c], acc[r][c]);
    }

    #pragma unroll
    for (int r = 0; r < 8; r++) {
        int row = row0 + rg * 8 + r;
        if (row < M) {
            #pragma unroll
            for (int c4 = 0; c4 < CPT / 4; c4++) {
                float4 o = make_float4(acc[r][c4*4+0], acc[r][c4*4+1],
                                       acc[r][c4*4+2], acc[r][c4*4+3]);
                *(float4*)(C + (size_t)row * P + cg * CPT + c4 * 4) = o;
            }
        }
    }
}

// ---------------- per-node attention logits --------------------------------
__global__ __launch_bounds__(256)
void attn_kernel(const float* __restrict__ hp,
                 const float* __restrict__ asrc, const float* __restrict__ atrg,
                 float* __restrict__ as_, float* __restrict__ at_)
{
    int w    = (blockIdx.x * blockDim.x + threadIdx.x) >> 5;
    int lane = threadIdx.x & 31;
    if (w >= N_NODES) return;
    int h = lane >> 4, sub = lane & 15;

    float4 v  = *(const float4*)(hp + (size_t)w * 128 + lane * 4);
    float4 s4 = *(const float4*)(asrc + lane * 4);
    float4 t4 = *(const float4*)(atrg + lane * 4);
    float ps = v.x*s4.x + v.y*s4.y + v.z*s4.z + v.w*s4.w;
    float pt = v.x*t4.x + v.y*t4.y + v.z*t4.z + v.w*t4.w;
    #pragma unroll
    for (int o = 8; o > 0; o >>= 1) {
        ps += __shfl_xor_sync(0xffffffffu, ps, o);
        pt += __shfl_xor_sync(0xffffffffu, pt, o);
    }
    if (sub == 0) {
        as_[w * 2 + h] = ps;
        at_[w * 2 + h] = pt;
    }
}

// ---------------- CSR build: zero / hist / scan / scatter ------------------
__global__ void zero_cnt_kernel(int* __restrict__ cnt)
{
    int i = blockIdx.x * blockDim.x + threadIdx.x;
    if (i < NUSER * 2) cnt[i] = 0;
}

__global__ __launch_bounds__(256)
void hist_kernel(const int* __restrict__ trg, int* __restrict__ cnt)
{
    int i = blockIdx.x * blockDim.x + threadIdx.x;
    if (i >= N_EDGES) return;
    int t = __ldg(trg + i);
    if (t < NUSER) atomicAdd(cnt + t, 1);
}

// per-block exclusive scan of 512-element chunks; partials[b] = chunk total
__global__ __launch_bounds__(256)
void scan1_kernel(const int* __restrict__ cnt, int* __restrict__ off,
                  int* __restrict__ part)
{
    __shared__ int s[256];
    int t = threadIdx.x, b = blockIdx.x;
    int i0 = b * SCAN_CHUNK + t * 2;
    int c0 = (i0     < NUSER) ? cnt[i0]     : 0;
    int c1 = (i0 + 1 < NUSER) ? cnt[i0 + 1] : 0;
    s[t] = c0 + c1;
    __syncthreads();
    int v = s[t];
    #pragma unroll
    for (int o = 1; o < 256; o <<= 1) {
        int u = (t >= o) ? s[t - o] : 0;
        __syncthreads();
        v += u; s[t] = v;
        __syncthreads();
    }
    int excl = v - (c0 + c1);
    if (i0     < NUSER) off[i0]     = excl;
    if (i0 + 1 < NUSER) off[i0 + 1] = excl + c0;
    if (t == 255) part[b] = v;
}

__global__ void scan2_kernel(int* __restrict__ part)
{
    __shared__ int s[256];
    int t = threadIdx.x;
    int own = (t < NPART) ? part[t] : 0;
    s[t] = own;
    __syncthreads();
    int v = s[t];
    #pragma unroll
    for (int o = 1; o < 256; o <<= 1) {
        int u = (t >= o) ? s[t - o] : 0;
        __syncthreads();
        v += u; s[t] = v;
        __syncthreads();
    }
    if (t < NPART) part[t] = v - own;
}

__global__ void scan3_kernel(int* __restrict__ off, const int* __restrict__ part)
{
    int i = blockIdx.x * blockDim.x + threadIdx.x;
    if (i < NUSER) off[i] += part[i / SCAN_CHUNK];
}

__global__ __launch_bounds__(256)
void scatter_kernel(const int* __restrict__ src, const int* __restrict__ trg,
                    const int* __restrict__ off, int* __restrict__ cur,
                    int* __restrict__ csr)
{
    int i = blockIdx.x * blockDim.x + threadIdx.x;
    if (i >= N_EDGES) return;
    int t = __ldg(trg + i);
    if (t >= NUSER) return;
    int pos = atomicAdd(cur + t, 1);
    csr[__ldg(off + t) + pos] = __ldg(src + i);
}

// ---------------- gather: warp per target, register accumulation -----------
// acc[f] = sum_e exp(leaky(as[s,h]+at[t,h])) * hp[s,h,f];  den = sum_e w
// then ta[t, layer, d] = 0.5 * (acc_h0[d]/den0 + acc_h1[d]/den1)
__global__ __launch_bounds__(256)
void gather_kernel(const int* __restrict__ csr, const int* __restrict__ off,
                   const int* __restrict__ cnt,
                   const float* __restrict__ as_, const float* __restrict__ at_,
                   const float* __restrict__ hp,
                   float* __restrict__ ta, int layer)
{
    int t    = (blockIdx.x * blockDim.x + threadIdx.x) >> 5;
    int lane = threadIdx.x & 31;
    if (t >= NUSER) return;
    int hsel = lane >> 4;                 // head of this lane

    float at_own = __ldg(at_ + 2 * t + hsel);
    int start = __ldg(off + t);
    int n     = __ldg(cnt + t);

    float4 acc = make_float4(0.f, 0.f, 0.f, 0.f);
    float  den = 0.f;

    #pragma unroll 2
    for (int i = 0; i < n; i++) {
        int s = __ldg(csr + start + i);
        float e = __ldg(as_ + 2 * s + hsel) + at_own;
        e = (e > 0.f) ? e : 0.2f * e;
        float w = __expf(e) ;
        // use precise expf to stay bit-close to reference
        w = expf(e);
        den += w;
        float4 v = *(const float4*)(hp + (size_t)s * 128 + lane * 4);
        acc.x = fmaf(w, v.x, acc.x);
        acc.y = fmaf(w, v.y, acc.y);
        acc.z = fmaf(w, v.z, acc.z);
        acc.w = fmaf(w, v.w, acc.w);
    }

    float inv = 1.f / (den + 1e-16f);
    acc.x *= inv; acc.y *= inv; acc.z *= inv; acc.w *= inv;

    // combine heads: lane L (head0) pairs with lane L+16 (head1), same dims
    float ox = __shfl_xor_sync(0xffffffffu, acc.x, 16);
    float oy = __shfl_xor_sync(0xffffffffu, acc.y, 16);
    float oz = __shfl_xor_sync(0xffffffffu, acc.z, 16);
    float ow = __shfl_xor_sync(0xffffffffu, acc.w, 16);
    if (hsel == 0) {
        float4 r = make_float4(0.5f * (acc.x + ox), 0.5f * (acc.y + oy),
                               0.5f * (acc.z + oz), 0.5f * (acc.w + ow));
        *(float4*)(ta + (size_t)t * 128 + layer * 64 + lane * 4) = r;
    }
}

// ---------------- head: tanh-attention fusion + FC + log_softmax ------------
__global__ __launch_bounds__(256)
void head_kernel(const float* __restrict__ u, const float* __restrict__ v,
                 const float* __restrict__ ta,
                 const float* __restrict__ aam, const float* __restrict__ fcw,
                 const float* __restrict__ fcb, float* __restrict__ outp)
{
    int w    = (blockIdx.x * blockDim.x + threadIdx.x) >> 5;
    int lane = threadIdx.x & 31;
    if (w >= NUSER) return;
    int d1 = lane, d2 = lane + 32;

    float u1   = u[w * 64 + d1],            u2   = u[w * 64 + d2];
    float v01  = v[(2*w) * 64 + d1],        v02  = v[(2*w) * 64 + d2];
    float v11  = v[(2*w+1) * 64 + d1],      v12  = v[(2*w+1) * 64 + d2];
    float ta01 = ta[w * 128 + d1],          ta02 = ta[w * 128 + d2];
    float ta11 = ta[w * 128 + 64 + d1],     ta12 = ta[w * 128 + 64 + d2];
    float am1  = __ldg(aam + d1),           am2  = __ldg(aam + d2);

    float s0 = tanhf(u1 + v01) * am1 + tanhf(u2 + v02) * am2;
    float s1 = tanhf(u1 + v11) * am1 + tanhf(u2 + v12) * am2;
    #pragma unroll
    for (int o = 16; o > 0; o >>= 1) {
        s0 += __shfl_xor_sync(0xffffffffu, s0, o);
        s1 += __shfl_xor_sync(0xffffffffu, s1, o);
    }
    float m  = fmaxf(s0, s1);
    float e0 = expf(s0 - m), e1 = expf(s1 - m);
    float rb = 1.f / (e0 + e1);
    float b0 = e0 * rb, b1 = e1 * rb;

    float f1 = b0 * ta01 + b1 * ta11;
    float f2 = b0 * ta02 + b1 * ta12;

    float l0 = ta01 * __ldg(fcw + d1)        + ta02 * __ldg(fcw + d2)
             + ta11 * __ldg(fcw + 64 + d1)   + ta12 * __ldg(fcw + 64 + d2)
             + f1   * __ldg(fcw + 128 + d1)  + f2   * __ldg(fcw + 128 + d2);
    float l1 = ta01 * __ldg(fcw + 192 + d1)  + ta02 * __ldg(fcw + 192 + d2)
             + ta11 * __ldg(fcw + 256 + d1)  + ta12 * __ldg(fcw + 256 + d2)
             + f1   * __ldg(fcw + 320 + d1)  + f2   * __ldg(fcw + 320 + d2);
    #pragma unroll
    for (int o = 16; o > 0; o >>= 1) {
        l0 += __shfl_xor_sync(0xffffffffu, l0, o);
        l1 += __shfl_xor_sync(0xffffffffu, l1, o);
    }
    if (lane == 0) {
        l0 += __ldg(fcb + 0);
        l1 += __ldg(fcb + 1);
        float mm  = fmaxf(l0, l1);
        float lse = mm + logf(expf(l0 - mm) + expf(l1 - mm));
        outp[w * 2]     = l0 - lse;
        outp[w * 2 + 1] = l1 - lse;
    }
}

// ---------------- launch ----------------------------------------------------
extern "C" void kernel_launch(void* const* d_in, const int* in_sizes, int n_in,
                              void* d_out, int out_size)
{
    const float* h     = (const float*)d_in[0];
    const int*   src0  = (const int*)  d_in[1];
    const int*   trg0  = (const int*)  d_in[2];
    const int*   src1  = (const int*)  d_in[3];
    const int*   trg1  = (const int*)  d_in[4];
    const float* w0    = (const float*)d_in[5];
    const float* asrc0 = (const float*)d_in[6];
    const float* atrg0 = (const float*)d_in[7];
    const float* w1    = (const float*)d_in[8];
    const float* asrc1 = (const float*)d_in[9];
    const float* atrg1 = (const float*)d_in[10];
    const float* aaw1  = (const float*)d_in[11];
    const float* aaw2  = (const float*)d_in[12];
    const float* aam   = (const float*)d_in[13];
    const float* fcw   = (const float*)d_in[14];
    const float* fcb   = (const float*)d_in[15];
    float* out = (float*)d_out;

    float *hp, *as_, *at_, *ta, *u, *v;
    int *cnt, *off, *part, *csr;
    cudaGetSymbolAddress((void**)&hp,   g_hp);
    cudaGetSymbolAddress((void**)&as_,  g_as);
    cudaGetSymbolAddress((void**)&at_,  g_at);
    cudaGetSymbolAddress((void**)&ta,   g_ta);
    cudaGetSymbolAddress((void**)&u,    g_u);
    cudaGetSymbolAddress((void**)&v,    g_v);
    cudaGetSymbolAddress((void**)&cnt,  g_cnt);
    cudaGetSymbolAddress((void**)&off,  g_off);
    cudaGetSymbolAddress((void**)&part, g_part);
    cudaGetSymbolAddress((void**)&csr,  g_csr);
    int* cur = cnt + NUSER;

    const int SM128 = (64 * 132 + 64 * 128) * 4;
    const int SM64  = (64 * 132 + 64 * 64)  * 4;
    cudaFuncSetAttribute(gemm64<128,0>, cudaFuncAttributeMaxDynamicSharedMemorySize, SM128);
    cudaFuncSetAttribute(gemm64<64,1>,  cudaFuncAttributeMaxDynamicSharedMemorySize, SM64);

    const int GEMM_HP_BLK = (N_NODES + 127) / 128;
    const int ATTN_BLK    = N_NODES * 32 / 256;
    const int EDGE_BLK    = (N_EDGES + 255) / 256;
    const int GATH_BLK    = (NUSER * 32 + 255) / 256;
    const int HEAD_BLK    = NUSER * 32 / 256;

    for (int layer = 0; layer < 2; layer++) {
        const float* wL  = layer ? w1    : w0;
        const float* aS  = layer ? asrc1 : asrc0;
        const float* aT  = layer ? atrg1 : atrg0;
        const int*   sE  = layer ? src1  : src0;
        const int*   tE  = layer ? trg1  : trg0;

        gemm64<128,0><<<GEMM_HP_BLK, 256, SM128>>>(h, wL, hp, N_NODES);
        attn_kernel<<<ATTN_BLK, 256>>>(hp, aS, aT, as_, at_);

        zero_cnt_kernel<<<(NUSER * 2 + 255) / 256, 256>>>(cnt);
        hist_kernel<<<EDGE_BLK, 256>>>(tE, cnt);
        scan1_kernel<<<NPART, 256>>>(cnt, off, part);
        scan2_kernel<<<1, 256>>>(part);
        scan3_kernel<<<(NUSER + 255) / 256, 256>>>(off, part);
        scatter_kernel<<<EDGE_BLK, 256>>>(sE, tE, off, cur, csr);

        gather_kernel<<<GATH_BLK, 256>>>(csr, off, cnt, as_, at_, hp, ta, layer);
    }

    gemm64<64,1><<<(NUSER + 127) / 128, 256, SM64>>>(h, aaw1, u, NUSER);
    gemm64<64,1><<<(NUSER * 2 + 127) / 128, 256, SM64>>>(ta, aaw2, v, NUSER * 2);
    head_kernel<<<HEAD_BLK, 256>>>(u, v, ta, aam, fcw, fcb, out);

    (void)in_sizes; (void)n_in; (void)out_size;
}

// round 3
// speedup vs baseline: 2.0154x; 1.1187x over previous
#include <cuda_runtime.h>
#include <cuda_fp16.h>
#include <math.h>

#define N_NODES 100000
#define N_EDGES 1600000
#define NUSER   90000
#define NT2     (2 * NUSER)            // merged counter count = 180000
#define SCAN_CHUNK 1024
#define NPART   ((NT2 + SCAN_CHUNK - 1) / SCAN_CHUNK)   // 176

// ---------------- scratch (device globals; no allocation allowed) ----------
__device__ __align__(16) __half g_hp0[N_NODES * 128];   // layer0 hp, fp16
__device__ __align__(16) __half g_hp1[N_NODES * 128];   // layer1 hp, fp16
__device__ __align__(16) float g_as [2 * N_NODES * 2];  // [layer][n*2+h]
__device__ __align__(16) float g_at [2 * N_NODES * 2];
__device__ __align__(16) float g_ta [NUSER  * 128];     // type_aware (n, k, d)
__device__ __align__(16) float g_u  [NUSER  * 64];
__device__ __align__(16) float g_v  [NUSER  * 128];
__device__ __align__(16) int   g_cnt[2 * NT2];          // [0:NT2)=counts, [NT2:2*NT2)=cursor
__device__ __align__(16) int   g_off[NT2];
__device__ __align__(16) int   g_part[256];
__device__ __align__(16) int   g_csr[2 * N_EDGES];      // bucketed src ids (both layers)

// ---------------- fused hp GEMM + attn logits -------------------------------
// blockIdx.y = layer. hp(half) = h @ W ; as/at = per-row dots with asrc/atrg.
__global__ __launch_bounds__(256)
void gemm_hp_fused(const float* __restrict__ A,
                   const float* __restrict__ W0, const float* __restrict__ W1,
                   const float* __restrict__ asrc0, const float* __restrict__ atrg0,
                   const float* __restrict__ asrc1, const float* __restrict__ atrg1,
                   __half* __restrict__ hp0, __half* __restrict__ hp1,
                   float* __restrict__ asOut, float* __restrict__ atOut, int M)
{
    constexpr int P   = 128;
    constexpr int BM  = 128;
    constexpr int LDA = BM + 4;

    const int layer = blockIdx.y;
    const float* Braw = layer ? W1 : W0;
    const float* aS   = layer ? asrc1 : asrc0;
    const float* aT   = layer ? atrg1 : atrg0;
    __half* hpL = layer ? hp1 : hp0;

    extern __shared__ float smem[];
    float* As = smem;                        // [64][LDA]
    float* Bs = smem + 64 * LDA;             // [64][128]

    const int t    = threadIdx.x;
    const int row0 = blockIdx.x * BM;

    #pragma unroll 4
    for (int i = t; i < 64 * P; i += 256) {
        int kk = i >> 7, c = i & 127;
        Bs[kk * P + c] = Braw[(c >> 6) * 4096 + kk * 64 + (c & 63)];
    }
    #pragma unroll 4
    for (int i = t; i < BM * 16; i += 256) {
        int r  = i >> 4;
        int k4 = (i & 15) << 2;
        float4 a = make_float4(0.f, 0.f, 0.f, 0.f);
        if (row0 + r < M) a = *(const float4*)(A + (size_t)(row0 + r) * 64 + k4);
        As[(k4 + 0) * LDA + r] = a.x;
        As[(k4 + 1) * LDA + r] = a.y;
        As[(k4 + 2) * LDA + r] = a.z;
        As[(k4 + 3) * LDA + r] = a.w;
    }
    __syncthreads();

    const int cg = t & 15;
    const int rg = t >> 4;

    float acc[8][8];
    #pragma unroll
    for (int r = 0; r < 8; r++)
        #pragma unroll
        for (int c = 0; c < 8; c++) acc[r][c] = 0.f;

    #pragma unroll
    for (int k = 0; k < 64; k++) {
        float4 a0 = *(const float4*)(As + k * LDA + rg * 8);
        float4 a1 = *(const float4*)(As + k * LDA + rg * 8 + 4);
        float a[8] = {a0.x, a0.y, a0.z, a0.w, a1.x, a1.y, a1.z, a1.w};
        float4 b0 = *(const float4*)(Bs + k * P + cg * 8);
        float4 b1 = *(const float4*)(Bs + k * P + cg * 8 + 4);
        float b[8] = {b0.x, b0.y, b0.z, b0.w, b1.x, b1.y, b1.z, b1.w};
        #pragma unroll
        for (int r = 0; r < 8; r++)
            #pragma unroll
            for (int c = 0; c < 8; c++)
                acc[r][c] = fmaf(a[r], b[c], acc[r][c]);
    }

    // ---- write hp in fp16 ----
    #pragma unroll
    for (int r = 0; r < 8; r++) {
        int row = row0 + rg * 8 + r;
        if (row < M) {
            union { __half2 h2[4]; uint4 u4; } pk;
            #pragma unroll
            for (int c2 = 0; c2 < 4; c2++)
                pk.h2[c2] = __floats2half2_rn(acc[r][2*c2], acc[r][2*c2+1]);
            *(uint4*)(hpL + (size_t)row * 128 + cg * 8) = pk.u4;
        }
    }

    // ---- attn logits: per-row dot with asrc/atrg, reduce across 8-lane group
    float4 s0 = *(const float4*)(aS + cg * 8);
    float4 s1 = *(const float4*)(aS + cg * 8 + 4);
    float4 t0 = *(const float4*)(aT + cg * 8);
    float4 t1 = *(const float4*)(aT + cg * 8 + 4);
    float sv[8] = {s0.x, s0.y, s0.z, s0.w, s1.x, s1.y, s1.z, s1.w};
    float tv[8] = {t0.x, t0.y, t0.z, t0.w, t1.x, t1.y, t1.z, t1.w};

    float pas[8], pat[8];
    #pragma unroll
    for (int r = 0; r < 8; r++) {
        float a_ = 0.f, b_ = 0.f;
        #pragma unroll
        for (int c = 0; c < 8; c++) {
            a_ = fmaf(acc[r][c], sv[c], a_);
            b_ = fmaf(acc[r][c], tv[c], b_);
        }
        pas[r] = a_; pat[r] = b_;
    }
    #pragma unroll
    for (int o = 1; o < 8; o <<= 1) {
        #pragma unroll
        for (int r = 0; r < 8; r++) {
            pas[r] += __shfl_xor_sync(0xffffffffu, pas[r], o);
            pat[r] += __shfl_xor_sync(0xffffffffu, pat[r], o);
        }
    }
    if ((cg & 7) == 0) {
        int head  = cg >> 3;
        int abase = layer * N_NODES * 2;
        #pragma unroll
        for (int r = 0; r < 8; r++) {
            int row = row0 + rg * 8 + r;
            if (row < M) {
                asOut[abase + row * 2 + head] = pas[r];
                atOut[abase + row * 2 + head] = pat[r];
            }
        }
    }
}

// ---------------- small GEMM for head: C[M x 64] = A[M x 64] @ Braw^T -------
__global__ __launch_bounds__(256)
void gemm64t(const float* __restrict__ A, const float* __restrict__ Braw,
             float* __restrict__ C, int M)
{
    constexpr int P   = 64;
    constexpr int BM  = 128;
    constexpr int LDA = BM + 4;

    extern __shared__ float smem[];
    float* As = smem;
    float* Bs = smem + 64 * LDA;

    const int t    = threadIdx.x;
    const int row0 = blockIdx.x * BM;

    #pragma unroll 4
    for (int i = t; i < 64 * P; i += 256) {
        int kk = i / P, c = i % P;
        Bs[kk * P + c] = Braw[c * 64 + kk];
    }
    #pragma unroll 4
    for (int i = t; i < BM * 16; i += 256) {
        int r  = i >> 4;
        int k4 = (i & 15) << 2;
        float4 a = make_float4(0.f, 0.f, 0.f, 0.f);
        if (row0 + r < M) a = *(const float4*)(A + (size_t)(row0 + r) * 64 + k4);
        As[(k4 + 0) * LDA + r] = a.x;
        As[(k4 + 1) * LDA + r] = a.y;
        As[(k4 + 2) * LDA + r] = a.z;
        As[(k4 + 3) * LDA + r] = a.w;
    }
    __syncthreads();

    const int cg = t & 15;
    const int rg = t >> 4;

    float acc[8][4];
    #pragma unroll
    for (int r = 0; r < 8; r++)
        #pragma unroll
        for (int c = 0; c < 4; c++) acc[r][c] = 0.f;

    #pragma unroll
    for (int k = 0; k < 64; k++) {
        float4 a0 = *(const float4*)(As + k * LDA + rg * 8);
        float4 a1 = *(const float4*)(As + k * LDA + rg * 8 + 4);
        float a[8] = {a0.x, a0.y, a0.z, a0.w, a1.x, a1.y, a1.z, a1.w};
        float4 b0 = *(const float4*)(Bs + k * P + cg * 4);
        float b[4] = {b0.x, b0.y, b0.z, b0.w};
        #pragma unroll
        for (int r = 0; r < 8; r++)
            #pragma unroll
            for (int c = 0; c < 4; c++)
                acc[r][c] = fmaf(a[r], b[c], acc[r][c]);
    }

    #pragma unroll
    for (int r = 0; r < 8; r++) {
        int row = row0 + rg * 8 + r;
        if (row < M) {
            float4 o = make_float4(acc[r][0], acc[r][1], acc[r][2], acc[r][3]);
            *(float4*)(C + (size_t)row * P + cg * 4) = o;
        }
    }
}

// ---------------- CSR build (both layers merged) ----------------------------
__global__ void zero_cnt_kernel(int* __restrict__ cnt)
{
    int i = blockIdx.x * blockDim.x + threadIdx.x;
    if (i < 2 * NT2) cnt[i] = 0;
}

__global__ __launch_bounds__(256)
void hist_kernel(const int* __restrict__ trgA, const int* __restrict__ trgB,
                 int* __restrict__ cnt)
{
    int i = blockIdx.x * blockDim.x + threadIdx.x;
    if (i >= 2 * N_EDGES) return;
    int layer = (i >= N_EDGES);
    const int* trg = layer ? trgB : trgA;
    int t = __ldg(trg + (i - layer * N_EDGES));
    if (t < NUSER) atomicAdd(cnt + layer * NUSER + t, 1);
}

// scan over NT2 counters: 1024-chunks, 256 threads x 4 elems
__global__ __launch_bounds__(256)
void scan1_kernel(const int* __restrict__ cnt, int* __restrict__ off,
                  int* __restrict__ part)
{
    __shared__ int s[256];
    int t = threadIdx.x, b = blockIdx.x;
    int i0 = b * SCAN_CHUNK + t * 4;
    int c[4];
    #pragma unroll
    for (int j = 0; j < 4; j++) c[j] = (i0 + j < NT2) ? cnt[i0 + j] : 0;
    int tot = c[0] + c[1] + c[2] + c[3];
    s[t] = tot;
    __syncthreads();
    int v = s[t];
    #pragma unroll
    for (int o = 1; o < 256; o <<= 1) {
        int u = (t >= o) ? s[t - o] : 0;
        __syncthreads();
        v += u; s[t] = v;
        __syncthreads();
    }
    int excl = v - tot;
    #pragma unroll
    for (int j = 0; j < 4; j++) {
        if (i0 + j < NT2) off[i0 + j] = excl;
        excl += c[j];
    }
    if (t == 255) part[b] = v;
}

__global__ void scan2_kernel(int* __restrict__ part)
{
    __shared__ int s[256];
    int t = threadIdx.x;
    int own = (t < NPART) ? part[t] : 0;
    s[t] = own;
    __syncthreads();
    int v = s[t];
    #pragma unroll
    for (int o = 1; o < 256; o <<= 1) {
        int u = (t >= o) ? s[t - o] : 0;
        __syncthreads();
        v += u; s[t] = v;
        __syncthreads();
    }
    if (t < NPART) part[t] = v - own;
}

__global__ void scan3_kernel(int* __restrict__ off, const int* __restrict__ part)
{
    int i = blockIdx.x * blockDim.x + threadIdx.x;
    if (i < NT2) off[i] += part[i / SCAN_CHUNK];
}

__global__ __launch_bounds__(256)
void scatter_kernel(const int* __restrict__ srcA, const int* __restrict__ trgA,
                    const int* __restrict__ srcB, const int* __restrict__ trgB,
                    const int* __restrict__ off, int* __restrict__ cur,
                    int* __restrict__ csr)
{
    int i = blockIdx.x * blockDim.x + threadIdx.x;
    if (i >= 2 * N_EDGES) return;
    int layer = (i >= N_EDGES);
    int e = i - layer * N_EDGES;
    const int* trg = layer ? trgB : trgA;
    const int* src = layer ? srcB : srcA;
    int t = __ldg(trg + e);
    if (t >= NUSER) return;
    int bucket = layer * NUSER + t;
    int pos = atomicAdd(cur + bucket, 1);
    csr[__ldg(off + bucket) + pos] = __ldg(src + e);
}

// ---------------- gather: warp per (layer, target) --------------------------
__global__ __launch_bounds__(256)
void gather_kernel(const int* __restrict__ csr, const int* __restrict__ off,
                   const int* __restrict__ cnt,
                   const float* __restrict__ as_, const float* __restrict__ at_,
                   const __half* __restrict__ hp0, const __half* __restrict__ hp1,
                   float* __restrict__ ta)
{
    int w    = (blockIdx.x * blockDim.x + threadIdx.x) >> 5;
    int lane = threadIdx.x & 31;
    if (w >= 2 * NUSER) return;
    int layer = (w >= NUSER);
    int t = w - layer * NUSER;
    const __half* hpL = layer ? hp1 : hp0;
    int abase = layer * N_NODES * 2;
    int hsel  = lane >> 4;

    float at_own = __ldg(at_ + abase + 2 * t + hsel);
    int bucket = layer * NUSER + t;
    int start  = __ldg(off + bucket);
    int n      = __ldg(cnt + bucket);

    float4 acc = make_float4(0.f, 0.f, 0.f, 0.f);
    float  den = 0.f;

    #pragma unroll 2
    for (int i = 0; i < n; i++) {
        int s = __ldg(csr + start + i);
        float e = __ldg(as_ + abase + 2 * s + hsel) + at_own;
        e = (e > 0.f) ? e : 0.2f * e;
        float wgt = expf(e);
        den += wgt;
        uint2 raw = *(const uint2*)(hpL + (size_t)s * 128 + lane * 4);
        float2 fa = __half22float2(*reinterpret_cast<__half2*>(&raw.x));
        float2 fb = __half22float2(*reinterpret_cast<__half2*>(&raw.y));
        acc.x = fmaf(wgt, fa.x, acc.x);
        acc.y = fmaf(wgt, fa.y, acc.y);
        acc.z = fmaf(wgt, fb.x, acc.z);
        acc.w = fmaf(wgt, fb.y, acc.w);
    }

    float inv = 1.f / (den + 1e-16f);
    acc.x *= inv; acc.y *= inv; acc.z *= inv; acc.w *= inv;

    float ox = __shfl_xor_sync(0xffffffffu, acc.x, 16);
    float oy = __shfl_xor_sync(0xffffffffu, acc.y, 16);
    float oz = __shfl_xor_sync(0xffffffffu, acc.z, 16);
    float ow = __shfl_xor_sync(0xffffffffu, acc.w, 16);
    if (hsel == 0) {
        float4 r = make_float4(0.5f * (acc.x + ox), 0.5f * (acc.y + oy),
                               0.5f * (acc.z + oz), 0.5f * (acc.w + ow));
        *(float4*)(ta + (size_t)t * 128 + layer * 64 + lane * 4) = r;
    }
}

// ---------------- head: tanh-attention fusion + FC + log_softmax ------------
__global__ __launch_bounds__(256)
void head_kernel(const float* __restrict__ u, const float* __restrict__ v,
                 const float* __restrict__ ta,
                 const float* __restrict__ aam, const float* __restrict__ fcw,
                 const float* __restrict__ fcb, float* __restrict__ outp)
{
    int w    = (blockIdx.x * blockDim.x + threadIdx.x) >> 5;
    int lane = threadIdx.x & 31;
    if (w >= NUSER) return;
    int d1 = lane, d2 = lane + 32;

    float u1   = u[w * 64 + d1],            u2   = u[w * 64 + d2];
    float v01  = v[(2*w) * 64 + d1],        v02  = v[(2*w) * 64 + d2];
    float v11  = v[(2*w+1) * 64 + d1],      v12  = v[(2*w+1) * 64 + d2];
    float ta01 = ta[w * 128 + d1],          ta02 = ta[w * 128 + d2];
    float ta11 = ta[w * 128 + 64 + d1],     ta12 = ta[w * 128 + 64 + d2];
    float am1  = __ldg(aam + d1),           am2  = __ldg(aam + d2);

    float s0 = tanhf(u1 + v01) * am1 + tanhf(u2 + v02) * am2;
    float s1 = tanhf(u1 + v11) * am1 + tanhf(u2 + v12) * am2;
    #pragma unroll
    for (int o = 16; o > 0; o >>= 1) {
        s0 += __shfl_xor_sync(0xffffffffu, s0, o);
        s1 += __shfl_xor_sync(0xffffffffu, s1, o);
    }
    float m  = fmaxf(s0, s1);
    float e0 = expf(s0 - m), e1 = expf(s1 - m);
    float rb = 1.f / (e0 + e1);
    float b0 = e0 * rb, b1 = e1 * rb;

    float f1 = b0 * ta01 + b1 * ta11;
    float f2 = b0 * ta02 + b1 * ta12;

    float l0 = ta01 * __ldg(fcw + d1)        + ta02 * __ldg(fcw + d2)
             + ta11 * __ldg(fcw + 64 + d1)   + ta12 * __ldg(fcw + 64 + d2)
             + f1   * __ldg(fcw + 128 + d1)  + f2   * __ldg(fcw + 128 + d2);
    float l1 = ta01 * __ldg(fcw + 192 + d1)  + ta02 * __ldg(fcw + 192 + d2)
             + ta11 * __ldg(fcw + 256 + d1)  + ta12 * __ldg(fcw + 256 + d2)
             + f1   * __ldg(fcw + 320 + d1)  + f2   * __ldg(fcw + 320 + d2);
    #pragma unroll
    for (int o = 16; o > 0; o >>= 1) {
        l0 += __shfl_xor_sync(0xffffffffu, l0, o);
        l1 += __shfl_xor_sync(0xffffffffu, l1, o);
    }
    if (lane == 0) {
        l0 += __ldg(fcb + 0);
        l1 += __ldg(fcb + 1);
        float mm  = fmaxf(l0, l1);
        float lse = mm + logf(expf(l0 - mm) + expf(l1 - mm));
        outp[w * 2]     = l0 - lse;
        outp[w * 2 + 1] = l1 - lse;
    }
}

// ---------------- launch ----------------------------------------------------
extern "C" void kernel_launch(void* const* d_in, const int* in_sizes, int n_in,
                              void* d_out, int out_size)
{
    const float* h     = (const float*)d_in[0];
    const int*   src0  = (const int*)  d_in[1];
    const int*   trg0  = (const int*)  d_in[2];
    const int*   src1  = (const int*)  d_in[3];
    const int*   trg1  = (const int*)  d_in[4];
    const float* w0    = (const float*)d_in[5];
    const float* asrc0 = (const float*)d_in[6];
    const float* atrg0 = (const float*)d_in[7];
    const float* w1    = (const float*)d_in[8];
    const float* asrc1 = (const float*)d_in[9];
    const float* atrg1 = (const float*)d_in[10];
    const float* aaw1  = (const float*)d_in[11];
    const float* aaw2  = (const float*)d_in[12];
    const float* aam   = (const float*)d_in[13];
    const float* fcw   = (const float*)d_in[14];
    const float* fcb   = (const float*)d_in[15];
    float* out = (float*)d_out;

    __half *hp0, *hp1;
    float *as_, *at_, *ta, *u, *v;
    int *cnt, *off, *part, *csr;
    cudaGetSymbolAddress((void**)&hp0,  g_hp0);
    cudaGetSymbolAddress((void**)&hp1,  g_hp1);
    cudaGetSymbolAddress((void**)&as_,  g_as);
    cudaGetSymbolAddress((void**)&at_,  g_at);
    cudaGetSymbolAddress((void**)&ta,   g_ta);
    cudaGetSymbolAddress((void**)&u,    g_u);
    cudaGetSymbolAddress((void**)&v,    g_v);
    cudaGetSymbolAddress((void**)&cnt,  g_cnt);
    cudaGetSymbolAddress((void**)&off,  g_off);
    cudaGetSymbolAddress((void**)&part, g_part);
    cudaGetSymbolAddress((void**)&csr,  g_csr);
    int* cur = cnt + NT2;

    const int SM128 = (64 * 132 + 64 * 128) * 4;
    const int SM64  = (64 * 132 + 64 * 64)  * 4;
    cudaFuncSetAttribute(gemm_hp_fused, cudaFuncAttributeMaxDynamicSharedMemorySize, SM128);
    cudaFuncSetAttribute(gemm64t,       cudaFuncAttributeMaxDynamicSharedMemorySize, SM64);

    const int EDGE2_BLK = (2 * N_EDGES + 255) / 256;
    const int GATH_BLK  = (2 * NUSER * 32 + 255) / 256;
    const int HEAD_BLK  = NUSER * 32 / 256;

    // CSR build for both layers (independent of GEMMs)
    zero_cnt_kernel<<<(2 * NT2 + 255) / 256, 256>>>(cnt);
    hist_kernel<<<EDGE2_BLK, 256>>>(trg0, trg1, cnt);
    scan1_kernel<<<NPART, 256>>>(cnt, off, part);
    scan2_kernel<<<1, 256>>>(part);
    scan3_kernel<<<(NT2 + 255) / 256, 256>>>(off, part);
    scatter_kernel<<<EDGE2_BLK, 256>>>(src0, trg0, src1, trg1, off, cur, csr);

    // hp GEMMs (both layers) with fused attention logits
    dim3 ggrid((N_NODES + 127) / 128, 2);
    gemm_hp_fused<<<ggrid, 256, SM128>>>(h, w0, w1, asrc0, atrg0, asrc1, atrg1,
                                         hp0, hp1, as_, at_, N_NODES);

    // gather both layers
    gather_kernel<<<GATH_BLK, 256>>>(csr, off, cnt, as_, at_, hp0, hp1, ta);

    // head
    gemm64t<<<(NUSER + 127) / 128, 256, SM64>>>(h, aaw1, u, NUSER);
    gemm64t<<<(NUSER * 2 + 127) / 128, 256, SM64>>>(ta, aaw2, v, NUSER * 2);
    head_kernel<<<HEAD_BLK, 256>>>(u, v, ta, aam, fcw, fcb, out);

    (void)in_sizes; (void)n_in; (void)out_size;
}

// round 4
// speedup vs baseline: 2.1790x; 1.0812x over previous
#include <cuda_runtime.h>
#include <cuda_fp16.h>
#include <math.h>

#define N_NODES 100000
#define N_EDGES 1600000
#define NUSER   90000
#define NT2     (2 * NUSER)            // merged bucket count = 180000
#define SCAN_CHUNK 1024
#define NPART   ((NT2 + SCAN_CHUNK - 1) / SCAN_CHUNK)   // 176

// ---------------- scratch (device globals; no allocation allowed) ----------
__device__ __align__(16) __half g_hp0[N_NODES * 128];
__device__ __align__(16) __half g_hp1[N_NODES * 128];
__device__ __align__(16) float g_as [2 * N_NODES * 2];  // [layer][n*2+h]
__device__ __align__(16) float g_at [2 * N_NODES * 2];
__device__ __align__(16) float g_ta [NUSER  * 128];     // type_aware (n, k, d)
__device__ __align__(16) float g_u  [NUSER  * 64];
__device__ __align__(16) float g_v  [NUSER  * 128];
__device__ __align__(16) int   g_cnt[NT2];              // counts
__device__ __align__(16) int   g_off[NT2];              // CSR offsets
__device__ __align__(16) int   g_cur[NT2];              // scatter cursors
__device__ __align__(16) int   g_part[256];
__device__ __align__(16) int   g_csr[2 * N_EDGES];

// ---------------- fused hp GEMM + attn logits -------------------------------
__global__ __launch_bounds__(256)
void gemm_hp_fused(const float* __restrict__ A,
                   const float* __restrict__ W0, const float* __restrict__ W1,
                   const float* __restrict__ asrc0, const float* __restrict__ atrg0,
                   const float* __restrict__ asrc1, const float* __restrict__ atrg1,
                   __half* __restrict__ hp0, __half* __restrict__ hp1,
                   float* __restrict__ asOut, float* __restrict__ atOut, int M)
{
    constexpr int P   = 128;
    constexpr int BM  = 128;
    constexpr int LDA = BM + 4;

    const int layer = blockIdx.y;
    const float* Braw = layer ? W1 : W0;
    const float* aS   = layer ? asrc1 : asrc0;
    const float* aT   = layer ? atrg1 : atrg0;
    __half* hpL = layer ? hp1 : hp0;

    extern __shared__ float smem[];
    float* As = smem;                        // [64][LDA]
    float* Bs = smem + 64 * LDA;             // [64][128]

    const int t    = threadIdx.x;
    const int row0 = blockIdx.x * BM;

    #pragma unroll 4
    for (int i = t; i < 64 * P; i += 256) {
        int kk = i >> 7, c = i & 127;
        Bs[kk * P + c] = Braw[(c >> 6) * 4096 + kk * 64 + (c & 63)];
    }
    #pragma unroll 4
    for (int i = t; i < BM * 16; i += 256) {
        int r  = i >> 4;
        int k4 = (i & 15) << 2;
        float4 a = make_float4(0.f, 0.f, 0.f, 0.f);
        if (row0 + r < M) a = *(const float4*)(A + (size_t)(row0 + r) * 64 + k4);
        As[(k4 + 0) * LDA + r] = a.x;
        As[(k4 + 1) * LDA + r] = a.y;
        As[(k4 + 2) * LDA + r] = a.z;
        As[(k4 + 3) * LDA + r] = a.w;
    }
    __syncthreads();

    const int cg = t & 15;
    const int rg = t >> 4;

    float acc[8][8];
    #pragma unroll
    for (int r = 0; r < 8; r++)
        #pragma unroll
        for (int c = 0; c < 8; c++) acc[r][c] = 0.f;

    #pragma unroll
    for (int k = 0; k < 64; k++) {
        float4 a0 = *(const float4*)(As + k * LDA + rg * 8);
        float4 a1 = *(const float4*)(As + k * LDA + rg * 8 + 4);
        float a[8] = {a0.x, a0.y, a0.z, a0.w, a1.x, a1.y, a1.z, a1.w};
        float4 b0 = *(const float4*)(Bs + k * P + cg * 8);
        float4 b1 = *(const float4*)(Bs + k * P + cg * 8 + 4);
        float b[8] = {b0.x, b0.y, b0.z, b0.w, b1.x, b1.y, b1.z, b1.w};
        #pragma unroll
        for (int r = 0; r < 8; r++)
            #pragma unroll
            for (int c = 0; c < 8; c++)
                acc[r][c] = fmaf(a[r], b[c], acc[r][c]);
    }

    #pragma unroll
    for (int r = 0; r < 8; r++) {
        int row = row0 + rg * 8 + r;
        if (row < M) {
            union { __half2 h2[4]; uint4 u4; } pk;
            #pragma unroll
            for (int c2 = 0; c2 < 4; c2++)
                pk.h2[c2] = __floats2half2_rn(acc[r][2*c2], acc[r][2*c2+1]);
            *(uint4*)(hpL + (size_t)row * 128 + cg * 8) = pk.u4;
        }
    }

    float4 s0 = *(const float4*)(aS + cg * 8);
    float4 s1 = *(const float4*)(aS + cg * 8 + 4);
    float4 t0 = *(const float4*)(aT + cg * 8);
    float4 t1 = *(const float4*)(aT + cg * 8 + 4);
    float sv[8] = {s0.x, s0.y, s0.z, s0.w, s1.x, s1.y, s1.z, s1.w};
    float tv[8] = {t0.x, t0.y, t0.z, t0.w, t1.x, t1.y, t1.z, t1.w};

    float pas[8], pat[8];
    #pragma unroll
    for (int r = 0; r < 8; r++) {
        float a_ = 0.f, b_ = 0.f;
        #pragma unroll
        for (int c = 0; c < 8; c++) {
            a_ = fmaf(acc[r][c], sv[c], a_);
            b_ = fmaf(acc[r][c], tv[c], b_);
        }
        pas[r] = a_; pat[r] = b_;
    }
    #pragma unroll
    for (int o = 1; o < 8; o <<= 1) {
        #pragma unroll
        for (int r = 0; r < 8; r++) {
            pas[r] += __shfl_xor_sync(0xffffffffu, pas[r], o);
            pat[r] += __shfl_xor_sync(0xffffffffu, pat[r], o);
        }
    }
    if ((cg & 7) == 0) {
        int head  = cg >> 3;
        int abase = layer * N_NODES * 2;
        #pragma unroll
        for (int r = 0; r < 8; r++) {
            int row = row0 + rg * 8 + r;
            if (row < M) {
                asOut[abase + row * 2 + head] = pas[r];
                atOut[abase + row * 2 + head] = pat[r];
            }
        }
    }
}

// ---------------- head GEMMs merged: y=0 -> u = h@aaw1^T ; y=1 -> v = ta@aaw2^T
__global__ __launch_bounds__(256)
void gemm_head(const float* __restrict__ A0, const float* __restrict__ B0,
               float* __restrict__ C0, int M0,
               const float* __restrict__ A1, const float* __restrict__ B1,
               float* __restrict__ C1, int M1)
{
    constexpr int P   = 64;
    constexpr int BM  = 128;
    constexpr int LDA = BM + 4;

    const int sel = blockIdx.y;
    const float* A    = sel ? A1 : A0;
    const float* Braw = sel ? B1 : B0;
    float*       C    = sel ? C1 : C0;
    const int    M    = sel ? M1 : M0;

    const int row0 = blockIdx.x * BM;
    if (row0 >= M) return;

    extern __shared__ float smem[];
    float* As = smem;
    float* Bs = smem + 64 * LDA;

    const int t = threadIdx.x;

    #pragma unroll 4
    for (int i = t; i < 64 * P; i += 256) {
        int kk = i / P, c = i % P;
        Bs[kk * P + c] = Braw[c * 64 + kk];
    }
    #pragma unroll 4
    for (int i = t; i < BM * 16; i += 256) {
        int r  = i >> 4;
        int k4 = (i & 15) << 2;
        float4 a = make_float4(0.f, 0.f, 0.f, 0.f);
        if (row0 + r < M) a = *(const float4*)(A + (size_t)(row0 + r) * 64 + k4);
        As[(k4 + 0) * LDA + r] = a.x;
        As[(k4 + 1) * LDA + r] = a.y;
        As[(k4 + 2) * LDA + r] = a.z;
        As[(k4 + 3) * LDA + r] = a.w;
    }
    __syncthreads();

    const int cg = t & 15;
    const int rg = t >> 4;

    float acc[8][4];
    #pragma unroll
    for (int r = 0; r < 8; r++)
        #pragma unroll
        for (int c = 0; c < 4; c++) acc[r][c] = 0.f;

    #pragma unroll
    for (int k = 0; k < 64; k++) {
        float4 a0 = *(const float4*)(As + k * LDA + rg * 8);
        float4 a1 = *(const float4*)(As + k * LDA + rg * 8 + 4);
        float a[8] = {a0.x, a0.y, a0.z, a0.w, a1.x, a1.y, a1.z, a1.w};
        float4 b0 = *(const float4*)(Bs + k * P + cg * 4);
        float b[4] = {b0.x, b0.y, b0.z, b0.w};
        #pragma unroll
        for (int r = 0; r < 8; r++)
            #pragma unroll
            for (int c = 0; c < 4; c++)
                acc[r][c] = fmaf(a[r], b[c], acc[r][c]);
    }

    #pragma unroll
    for (int r = 0; r < 8; r++) {
        int row = row0 + rg * 8 + r;
        if (row < M) {
            float4 o = make_float4(acc[r][0], acc[r][1], acc[r][2], acc[r][3]);
            *(float4*)(C + (size_t)row * P + cg * 4) = o;
        }
    }
}

// ---------------- CSR build --------------------------------------------------
__global__ void zero_cnt_kernel(int* __restrict__ cnt)
{
    int i = blockIdx.x * blockDim.x + threadIdx.x;
    if (i < NT2) cnt[i] = 0;
}

__global__ __launch_bounds__(256)
void hist_kernel(const int* __restrict__ trgA, const int* __restrict__ trgB,
                 int* __restrict__ cnt)
{
    int i = blockIdx.x * blockDim.x + threadIdx.x;
    if (i >= 2 * N_EDGES) return;
    int layer = (i >= N_EDGES);
    const int* trg = layer ? trgB : trgA;
    int t = __ldg(trg + (i - layer * N_EDGES));
    if (t < NUSER) atomicAdd(cnt + layer * NUSER + t, 1);
}

__global__ __launch_bounds__(256)
void scan1_kernel(const int* __restrict__ cnt, int* __restrict__ off,
                  int* __restrict__ part)
{
    __shared__ int s[256];
    int t = threadIdx.x, b = blockIdx.x;
    int i0 = b * SCAN_CHUNK + t * 4;
    int c[4];
    #pragma unroll
    for (int j = 0; j < 4; j++) c[j] = (i0 + j < NT2) ? cnt[i0 + j] : 0;
    int tot = c[0] + c[1] + c[2] + c[3];
    s[t] = tot;
    __syncthreads();
    int v = s[t];
    #pragma unroll
    for (int o = 1; o < 256; o <<= 1) {
        int u = (t >= o) ? s[t - o] : 0;
        __syncthreads();
        v += u; s[t] = v;
        __syncthreads();
    }
    int excl = v - tot;
    #pragma unroll
    for (int j = 0; j < 4; j++) {
        if (i0 + j < NT2) off[i0 + j] = excl;
        excl += c[j];
    }
    if (t == 255) part[b] = v;
}

__global__ void scan2_kernel(int* __restrict__ part)
{
    __shared__ int s[256];
    int t = threadIdx.x;
    int own = (t < NPART) ? part[t] : 0;
    s[t] = own;
    __syncthreads();
    int v = s[t];
    #pragma unroll
    for (int o = 1; o < 256; o <<= 1) {
        int u = (t >= o) ? s[t - o] : 0;
        __syncthreads();
        v += u; s[t] = v;
        __syncthreads();
    }
    if (t < NPART) part[t] = v - own;
}

// add chunk base AND initialize scatter cursor
__global__ void scan3_kernel(int* __restrict__ off, const int* __restrict__ part,
                             int* __restrict__ cur)
{
    int i = blockIdx.x * blockDim.x + threadIdx.x;
    if (i < NT2) {
        int o = off[i] + part[i / SCAN_CHUNK];
        off[i] = o;
        cur[i] = o;
    }
}

__global__ __launch_bounds__(256)
void scatter_kernel(const int* __restrict__ srcA, const int* __restrict__ trgA,
                    const int* __restrict__ srcB, const int* __restrict__ trgB,
                    int* __restrict__ cur, int* __restrict__ csr)
{
    int i = blockIdx.x * blockDim.x + threadIdx.x;
    if (i >= 2 * N_EDGES) return;
    int layer = (i >= N_EDGES);
    int e = i - layer * N_EDGES;
    const int* trg = layer ? trgB : trgA;
    const int* src = layer ? srcB : srcA;
    int t = __ldg(trg + e);
    if (t >= NUSER) return;
    int pos = atomicAdd(cur + layer * NUSER + t, 1);
    csr[pos] = __ldg(src + e);
}

// ---------------- gather: warp per (layer, target), 2 edges/iter ------------
// lanes [0,16) -> edge i, lanes [16,32) -> edge i+1
// within 16 lanes: sub covers halves [sub*8, sub*8+8); head = sub>>3
__global__ __launch_bounds__(256)
void gather_kernel(const int* __restrict__ csr, const int* __restrict__ off,
                   const int* __restrict__ cnt,
                   const float* __restrict__ as_, const float* __restrict__ at_,
                   const __half* __restrict__ hp0, const __half* __restrict__ hp1,
                   float* __restrict__ ta)
{
    int w    = (blockIdx.x * blockDim.x + threadIdx.x) >> 5;
    int lane = threadIdx.x & 31;
    if (w >= NT2) return;
    int layer = (w >= NUSER);
    int t = w - layer * NUSER;
    const __half* hpL = layer ? hp1 : hp0;
    int abase = layer * N_NODES * 2;

    int grp  = lane >> 4;        // which edge of the pair
    int sub  = lane & 15;        // 16-lane slot within edge
    int hsel = sub >> 3;         // head of this lane

    float at_own = __ldg(at_ + abase + 2 * t + hsel);
    int start = __ldg(off + w);
    int n     = __ldg(cnt + w);

    float acc[8];
    #pragma unroll
    for (int j = 0; j < 8; j++) acc[j] = 0.f;
    float den = 0.f;

    for (int i = 0; i < n; i += 2) {
        int idx = i + grp;
        bool valid = idx < n;
        int sidx = valid ? idx : i;                    // clamp (n>=1 here)
        int s = __ldg(csr + start + sidx);
        float e = __ldg(as_ + abase + 2 * s + hsel) + at_own;
        e = (e > 0.f) ? e : 0.2f * e;
        float wgt = valid ? __expf(e) : 0.f;
        den += wgt;
        uint4 raw = *(const uint4*)(hpL + (size_t)s * 128 + sub * 8);
        float2 f0 = __half22float2(*reinterpret_cast<__half2*>(&raw.x));
        float2 f1 = __half22float2(*reinterpret_cast<__half2*>(&raw.y));
        float2 f2 = __half22float2(*reinterpret_cast<__half2*>(&raw.z));
        float2 f3 = __half22float2(*reinterpret_cast<__half2*>(&raw.w));
        acc[0] = fmaf(wgt, f0.x, acc[0]);
        acc[1] = fmaf(wgt, f0.y, acc[1]);
        acc[2] = fmaf(wgt, f1.x, acc[2]);
        acc[3] = fmaf(wgt, f1.y, acc[3]);
        acc[4] = fmaf(wgt, f2.x, acc[4]);
        acc[5] = fmaf(wgt, f2.y, acc[5]);
        acc[6] = fmaf(wgt, f3.x, acc[6]);
        acc[7] = fmaf(wgt, f3.y, acc[7]);
    }

    // combine the two edge groups (lane ^ 16)
    den += __shfl_xor_sync(0xffffffffu, den, 16);
    #pragma unroll
    for (int j = 0; j < 8; j++)
        acc[j] += __shfl_xor_sync(0xffffffffu, acc[j], 16);

    float inv = 1.f / (den + 1e-16f);
    #pragma unroll
    for (int j = 0; j < 8; j++) acc[j] *= inv;

    // combine heads: lane ^ 8 pairs head0 dim d with head1 dim d
    float other[8];
    #pragma unroll
    for (int j = 0; j < 8; j++)
        other[j] = __shfl_xor_sync(0xffffffffu, acc[j], 8);

    if (grp == 0 && hsel == 0) {
        float4 r0 = make_float4(0.5f * (acc[0] + other[0]), 0.5f * (acc[1] + other[1]),
                                0.5f * (acc[2] + other[2]), 0.5f * (acc[3] + other[3]));
        float4 r1 = make_float4(0.5f * (acc[4] + other[4]), 0.5f * (acc[5] + other[5]),
                                0.5f * (acc[6] + other[6]), 0.5f * (acc[7] + other[7]));
        float* dst = ta + (size_t)t * 128 + layer * 64 + sub * 8;
        *(float4*)(dst)     = r0;
        *(float4*)(dst + 4) = r1;
    }
}

// ---------------- head: tanh-attention fusion + FC + log_softmax ------------
__global__ __launch_bounds__(256)
void head_kernel(const float* __restrict__ u, const float* __restrict__ v,
                 const float* __restrict__ ta,
                 const float* __restrict__ aam, const float* __restrict__ fcw,
                 const float* __restrict__ fcb, float* __restrict__ outp)
{
    int w    = (blockIdx.x * blockDim.x + threadIdx.x) >> 5;
    int lane = threadIdx.x & 31;
    if (w >= NUSER) return;
    int d1 = lane, d2 = lane + 32;

    float u1   = u[w * 64 + d1],            u2   = u[w * 64 + d2];
    float v01  = v[(2*w) * 64 + d1],        v02  = v[(2*w) * 64 + d2];
    float v11  = v[(2*w+1) * 64 + d1],      v12  = v[(2*w+1) * 64 + d2];
    float ta01 = ta[w * 128 + d1],          ta02 = ta[w * 128 + d2];
    float ta11 = ta[w * 128 + 64 + d1],     ta12 = ta[w * 128 + 64 + d2];
    float am1  = __ldg(aam + d1),           am2  = __ldg(aam + d2);

    float s0 = tanhf(u1 + v01) * am1 + tanhf(u2 + v02) * am2;
    float s1 = tanhf(u1 + v11) * am1 + tanhf(u2 + v12) * am2;
    #pragma unroll
    for (int o = 16; o > 0; o >>= 1) {
        s0 += __shfl_xor_sync(0xffffffffu, s0, o);
        s1 += __shfl_xor_sync(0xffffffffu, s1, o);
    }
    float m  = fmaxf(s0, s1);
    float e0 = expf(s0 - m), e1 = expf(s1 - m);
    float rb = 1.f / (e0 + e1);
    float b0 = e0 * rb, b1 = e1 * rb;

    float f1 = b0 * ta01 + b1 * ta11;
    float f2 = b0 * ta02 + b1 * ta12;

    float l0 = ta01 * __ldg(fcw + d1)        + ta02 * __ldg(fcw + d2)
             + ta11 * __ldg(fcw + 64 + d1)   + ta12 * __ldg(fcw + 64 + d2)
             + f1   * __ldg(fcw + 128 + d1)  + f2   * __ldg(fcw + 128 + d2);
    float l1 = ta01 * __ldg(fcw + 192 + d1)  + ta02 * __ldg(fcw + 192 + d2)
             + ta11 * __ldg(fcw + 256 + d1)  + ta12 * __ldg(fcw + 256 + d2)
             + f1   * __ldg(fcw + 320 + d1)  + f2   * __ldg(fcw + 320 + d2);
    #pragma unroll
    for (int o = 16; o > 0; o >>= 1) {
        l0 += __shfl_xor_sync(0xffffffffu, l0, o);
        l1 += __shfl_xor_sync(0xffffffffu, l1, o);
    }
    if (lane == 0) {
        l0 += __ldg(fcb + 0);
        l1 += __ldg(fcb + 1);
        float mm  = fmaxf(l0, l1);
        float lse = mm + logf(expf(l0 - mm) + expf(l1 - mm));
        outp[w * 2]     = l0 - lse;
        outp[w * 2 + 1] = l1 - lse;
    }
}

// ---------------- launch ----------------------------------------------------
extern "C" void kernel_launch(void* const* d_in, const int* in_sizes, int n_in,
                              void* d_out, int out_size)
{
    const float* h     = (const float*)d_in[0];
    const int*   src0  = (const int*)  d_in[1];
    const int*   trg0  = (const int*)  d_in[2];
    const int*   src1  = (const int*)  d_in[3];
    const int*   trg1  = (const int*)  d_in[4];
    const float* w0    = (const float*)d_in[5];
    const float* asrc0 = (const float*)d_in[6];
    const float* atrg0 = (const float*)d_in[7];
    const float* w1    = (const float*)d_in[8];
    const float* asrc1 = (const float*)d_in[9];
    const float* atrg1 = (const float*)d_in[10];
    const float* aaw1  = (const float*)d_in[11];
    const float* aaw2  = (const float*)d_in[12];
    const float* aam   = (const float*)d_in[13];
    const float* fcw   = (const float*)d_in[14];
    const float* fcb   = (const float*)d_in[15];
    float* out = (float*)d_out;

    __half *hp0, *hp1;
    float *as_, *at_, *ta, *u, *v;
    int *cnt, *off, *cur, *part, *csr;
    cudaGetSymbolAddress((void**)&hp0,  g_hp0);
    cudaGetSymbolAddress((void**)&hp1,  g_hp1);
    cudaGetSymbolAddress((void**)&as_,  g_as);
    cudaGetSymbolAddress((void**)&at_,  g_at);
    cudaGetSymbolAddress((void**)&ta,   g_ta);
    cudaGetSymbolAddress((void**)&u,    g_u);
    cudaGetSymbolAddress((void**)&v,    g_v);
    cudaGetSymbolAddress((void**)&cnt,  g_cnt);
    cudaGetSymbolAddress((void**)&off,  g_off);
    cudaGetSymbolAddress((void**)&cur,  g_cur);
    cudaGetSymbolAddress((void**)&part, g_part);
    cudaGetSymbolAddress((void**)&csr,  g_csr);

    const int SM128 = (64 * 132 + 64 * 128) * 4;
    const int SM64  = (64 * 132 + 64 * 64)  * 4;
    cudaFuncSetAttribute(gemm_hp_fused, cudaFuncAttributeMaxDynamicSharedMemorySize, SM128);
    cudaFuncSetAttribute(gemm_head,     cudaFuncAttributeMaxDynamicSharedMemorySize, SM64);

    const int EDGE2_BLK = (2 * N_EDGES + 255) / 256;
    const int GATH_BLK  = (NT2 * 32 + 255) / 256;
    const int HEAD_BLK  = NUSER * 32 / 256;

    // CSR build for both layers
    zero_cnt_kernel<<<(NT2 + 255) / 256, 256>>>(cnt);
    hist_kernel<<<EDGE2_BLK, 256>>>(trg0, trg1, cnt);
    scan1_kernel<<<NPART, 256>>>(cnt, off, part);
    scan2_kernel<<<1, 256>>>(part);
    scan3_kernel<<<(NT2 + 255) / 256, 256>>>(off, part, cur);
    scatter_kernel<<<EDGE2_BLK, 256>>>(src0, trg0, src1, trg1, cur, csr);

    // hp GEMMs (both layers) with fused attention logits
    dim3 ggrid((N_NODES + 127) / 128, 2);
    gemm_hp_fused<<<ggrid, 256, SM128>>>(h, w0, w1, asrc0, atrg0, asrc1, atrg1,
                                         hp0, hp1, as_, at_, N_NODES);

    // gather both layers
    gather_kernel<<<GATH_BLK, 256>>>(csr, off, cnt, as_, at_, hp0, hp1, ta);

    // head GEMMs (merged) + head
    dim3 hgrid((NUSER * 2 + 127) / 128, 2);
    gemm_head<<<hgrid, 256, SM64>>>(h, aaw1, u, NUSER, ta, aaw2, v, NUSER * 2);
    head_kernel<<<HEAD_BLK, 256>>>(u, v, ta, aam, fcw, fcb, out);

    (void)in_sizes; (void)n_in; (void)out_size;
}